// round 9
// baseline (speedup 1.0000x reference)
#include <cuda_runtime.h>
#include <cuda_fp16.h>
#include <cstdint>

// Problem constants (match reference)
#define NMAX      50000
#define EMAX      800000
#define IN_DIM    256
#define H_DIM     128
#define OUT_DIM   64
#define K_STEPS   10
#define ALPHA_F   0.1f

// Scale schedule: every prop divides stored values by 4 (exact, folded into
// fp32 scale constants). x_k true = y_k * (16 * 4^k); H true = Hs * 16.
#define PSCALE    4.0f

// -------- scratch (no allocation allowed -> device globals) --------
__device__ __half gX0[(size_t)NMAX * OUT_DIM];  // X @ (W1@W2)          (scale 1)
__device__ __half gP [(size_t)NMAX * OUT_DIM];  // (prop(X0)+c)/4       (scale 4)
__device__ __half gH [(size_t)NMAX * OUT_DIM];  // (prop(P)+b2)/16      (scale 16)
__device__ __half gA [(size_t)NMAX * OUT_DIM];  // ping  (scale 16*4^k)
__device__ __half gB [(size_t)NMAX * OUT_DIM];  // pong
__device__ float  gWc[IN_DIM * OUT_DIM];        // W1 @ W2  (256x64)
__device__ float  gC [OUT_DIM];                 // b1 @ W2
__device__ int    gIdxIs64;
// CSR scratch
__device__ int    gCount[NMAX];
__device__ int    gRowPtr[NMAX + 1];
__device__ int    gWp[NMAX];
// packed edge: low 16 = src (N<=65535), high 16 = fp16 weight bits
__device__ __align__(16) unsigned int gCsrP[EMAX];

// ------------- dtype detection: int64 vs int32 edge_index -------------
__global__ void detect_idx_dtype(const void* __restrict__ ei, int N)
{
    const long long* p = (const long long*)ei;
    int ok = 1;
    for (int i = 0; i < 64; i++) {
        long long v = p[i];
        if (v < 0 || v >= N) { ok = 0; break; }
    }
    gIdxIs64 = ok;
}

// ------------- CSR build -------------
__global__ void hist_dst(const void* __restrict__ ei, int E)
{
    int t = blockIdx.x * blockDim.x + threadIdx.x;
#pragma unroll
    for (int u = 0; u < 2; u++) {
        int e = t * 2 + u;
        if (e >= E) return;
        int d;
        if (gIdxIs64) d = (int)((const long long*)ei)[E + e];
        else          d = ((const int*)ei)[E + e];
        atomicAdd(&gCount[d], 1);
    }
}

__global__ void scan_rowptr(int N, int E)
{
    __shared__ int sSum[1024];
    const int tid = threadIdx.x;
    const int chunk = (N + 1023) / 1024;
    const int lo = tid * chunk;
    const int hi = min(lo + chunk, N);

    int s = 0;
    for (int i = lo; i < hi; i++) s += gCount[i];
    sSum[tid] = s;
    __syncthreads();

    for (int off = 1; off < 1024; off <<= 1) {
        int v = (tid >= off) ? sSum[tid - off] : 0;
        __syncthreads();
        sSum[tid] += v;
        __syncthreads();
    }
    int run = (tid == 0) ? 0 : sSum[tid - 1];
    for (int i = lo; i < hi; i++) {
        gRowPtr[i] = run;
        gWp[i]     = run;
        run += gCount[i];
    }
    if (tid == 1023) gRowPtr[N] = E;
}

__global__ void fill_csr(const void* __restrict__ ei, const float* __restrict__ ew, int E)
{
    int t = blockIdx.x * blockDim.x + threadIdx.x;
#pragma unroll
    for (int u = 0; u < 2; u++) {
        int e = t * 2 + u;
        if (e >= E) return;
        int s, d;
        if (gIdxIs64) {
            const long long* p = (const long long*)ei;
            s = (int)p[e];
            d = (int)p[E + e];
        } else {
            const int* p = (const int*)ei;
            s = p[e];
            d = p[E + e];
        }
        unsigned int wbits = (unsigned int)__half_as_ushort(__float2half_rn(ew[e]));
        int pos = atomicAdd(&gWp[d], 1);
        gCsrP[pos] = (unsigned int)s | (wbits << 16);
    }
}

// ------------- tiny: Wc = W1 @ W2 (256x64), c = b1 @ W2 (64) -------------
__global__ void combine_weights(const float* __restrict__ W1,
                                const float* __restrict__ b1,
                                const float* __restrict__ W2)
{
    int idx = blockIdx.x * blockDim.x + threadIdx.x;
    if (idx < IN_DIM * OUT_DIM) {
        int i = idx >> 6, j = idx & 63;
        float s = 0.0f;
        const float* w1r = W1 + (size_t)i * H_DIM;
#pragma unroll 8
        for (int k = 0; k < H_DIM; k++)
            s += w1r[k] * W2[(size_t)k * OUT_DIM + j];
        gWc[idx] = s;
    } else if (idx < IN_DIM * OUT_DIM + OUT_DIM) {
        int j = idx - IN_DIM * OUT_DIM;
        float s = 0.0f;
#pragma unroll 8
        for (int k = 0; k < H_DIM; k++)
            s += b1[k] * W2[(size_t)k * OUT_DIM + j];
        gC[j] = s;
    }
}

// ------------- tensor-core GEMM: X0[M,64] = fp16(A[M,256]) @ fp16(Wc[256,64]) ----
// 128 threads = 4 warps; block tile 64 rows; warp w handles rows 16w..16w+15.
// B (Wc) fully resident in smem; A streamed in 64-wide k-chunks.
__global__ void __launch_bounds__(128) gemm_mma(int M,
                                                const float* __restrict__ A,
                                                const float* __restrict__ Bw,
                                                __half* __restrict__ Ch)
{
    __shared__ __half As[64][72];
    __shared__ __half Bs[IN_DIM][72];

    const int tid  = threadIdx.x;
    const int wid  = tid >> 5;
    const int lane = tid & 31;
    const int rowBase = blockIdx.x * 64;

    // load full B (256x64 fp32 -> fp16)
#pragma unroll
    for (int i = 0; i < 32; i++) {
        int idx = tid + i * 128;        // 4096 float4
        int r = idx >> 4, cv = idx & 15;
        float4 v = *reinterpret_cast<const float4*>(Bw + r * 64 + cv * 4);
        __half2* dst = reinterpret_cast<__half2*>(&Bs[r][cv * 4]);
        dst[0] = __floats2half2_rn(v.x, v.y);
        dst[1] = __floats2half2_rn(v.z, v.w);
    }

    float acc[8][4];
#pragma unroll
    for (int n = 0; n < 8; n++)
#pragma unroll
        for (int j = 0; j < 4; j++) acc[n][j] = 0.0f;

    for (int c = 0; c < IN_DIM / 64; c++) {
        __syncthreads();
        // load A chunk: 64 rows x 64 cols fp32 -> fp16
#pragma unroll
        for (int i = 0; i < 8; i++) {
            int idx = tid + i * 128;    // 1024 float4
            int r = idx >> 4, cv = idx & 15;
            int grow = rowBase + r;
            float4 v = make_float4(0.f, 0.f, 0.f, 0.f);
            if (grow < M)
                v = *reinterpret_cast<const float4*>(A + (size_t)grow * IN_DIM + c * 64 + cv * 4);
            __half2* dst = reinterpret_cast<__half2*>(&As[r][cv * 4]);
            dst[0] = __floats2half2_rn(v.x, v.y);
            dst[1] = __floats2half2_rn(v.z, v.w);
        }
        __syncthreads();

#pragma unroll
        for (int k0 = 0; k0 < 64; k0 += 16) {
            uint32_t a0, a1, a2, a3;
            {
                uint32_t sa = (uint32_t)__cvta_generic_to_shared(
                    &As[16 * wid + (lane & 15)][k0 + 8 * (lane >> 4)]);
                asm volatile("ldmatrix.sync.aligned.m8n8.x4.shared.b16 {%0,%1,%2,%3}, [%4];"
                             : "=r"(a0), "=r"(a1), "=r"(a2), "=r"(a3) : "r"(sa));
            }
#pragma unroll
            for (int n = 0; n < 8; n++) {
                uint32_t b0, b1;
                uint32_t sb = (uint32_t)__cvta_generic_to_shared(
                    &Bs[c * 64 + k0 + (lane & 15)][n * 8]);
                asm volatile("ldmatrix.sync.aligned.m8n8.x2.trans.shared.b16 {%0,%1}, [%2];"
                             : "=r"(b0), "=r"(b1) : "r"(sb));
                asm volatile("mma.sync.aligned.m16n8k16.row.col.f32.f16.f16.f32 "
                             "{%0,%1,%2,%3}, {%4,%5,%6,%7}, {%8,%9}, {%0,%1,%2,%3};"
                             : "+f"(acc[n][0]), "+f"(acc[n][1]), "+f"(acc[n][2]), "+f"(acc[n][3])
                             : "r"(a0), "r"(a1), "r"(a2), "r"(a3), "r"(b0), "r"(b1));
            }
        }
    }

    // store: c0,c1 -> (row=lane/4, col=2*(lane%4)); c2,c3 -> row+8
    int row  = lane >> 2;
    int colp = (lane & 3) * 2;
#pragma unroll
    for (int n = 0; n < 8; n++) {
        int g0 = rowBase + 16 * wid + row;
        if (g0 < M)
            *reinterpret_cast<__half2*>(Ch + (size_t)g0 * 64 + n * 8 + colp) =
                __floats2half2_rn(acc[n][0], acc[n][1]);
        int g1 = g0 + 8;
        if (g1 < M)
            *reinterpret_cast<__half2*>(Ch + (size_t)g1 * 64 + n * 8 + colp) =
                __floats2half2_rn(acc[n][2], acc[n][3]);
    }
}

// ------------- CSR gather prop, DIM=64, fp16 x, packed 4B edges -------------
// out[n,:] = wscale*sum_e w_e*x[src_e,:] + ascale*addv[n,:] + bscale*bias[:]
// One warp per node; lane l owns half2 pair {2l, 2l+1}.
template<bool HALF_OUT>
__global__ void gather64h(const __half2* __restrict__ x,
                          void* __restrict__ outv,
                          const __half2* __restrict__ addv,  // may be null
                          const float* __restrict__ bias,    // fp32[64], may be null
                          int N, float wscale, float ascale, float bscale)
{
    int warp = (blockIdx.x * blockDim.x + threadIdx.x) >> 5;
    int lane = threadIdx.x & 31;
    if (warp >= N) return;

    int e   = gRowPtr[warp];
    int end = gRowPtr[warp + 1];

    float ax = 0.f, ay = 0.f;

    // peel to 16B alignment
    while ((e & 3) && e < end) {
        unsigned int v = __ldg(&gCsrP[e]);
        float w = __half2float(__ushort_as_half((unsigned short)(v >> 16)));
        float2 f = __half22float2(__ldg(x + (size_t)(v & 0xffffu) * 32 + lane));
        ax = fmaf(w, f.x, ax); ay = fmaf(w, f.y, ay);
        e++;
    }

    // 8 edges per iteration: 2 uint4 loads + 8 row loads in flight
    for (; e + 7 < end; e += 8) {
        uint4 c0 = __ldg(reinterpret_cast<const uint4*>(gCsrP + e));
        uint4 c1 = __ldg(reinterpret_cast<const uint4*>(gCsrP + e + 4));
        float2 f0 = __half22float2(__ldg(x + (size_t)(c0.x & 0xffffu) * 32 + lane));
        float2 f1 = __half22float2(__ldg(x + (size_t)(c0.y & 0xffffu) * 32 + lane));
        float2 f2 = __half22float2(__ldg(x + (size_t)(c0.z & 0xffffu) * 32 + lane));
        float2 f3 = __half22float2(__ldg(x + (size_t)(c0.w & 0xffffu) * 32 + lane));
        float2 f4 = __half22float2(__ldg(x + (size_t)(c1.x & 0xffffu) * 32 + lane));
        float2 f5 = __half22float2(__ldg(x + (size_t)(c1.y & 0xffffu) * 32 + lane));
        float2 f6 = __half22float2(__ldg(x + (size_t)(c1.z & 0xffffu) * 32 + lane));
        float2 f7 = __half22float2(__ldg(x + (size_t)(c1.w & 0xffffu) * 32 + lane));
        float w0 = __half2float(__ushort_as_half((unsigned short)(c0.x >> 16)));
        float w1 = __half2float(__ushort_as_half((unsigned short)(c0.y >> 16)));
        float w2 = __half2float(__ushort_as_half((unsigned short)(c0.z >> 16)));
        float w3 = __half2float(__ushort_as_half((unsigned short)(c0.w >> 16)));
        float w4 = __half2float(__ushort_as_half((unsigned short)(c1.x >> 16)));
        float w5 = __half2float(__ushort_as_half((unsigned short)(c1.y >> 16)));
        float w6 = __half2float(__ushort_as_half((unsigned short)(c1.z >> 16)));
        float w7 = __half2float(__ushort_as_half((unsigned short)(c1.w >> 16)));
        ax = fmaf(w0, f0.x, ax); ay = fmaf(w0, f0.y, ay);
        ax = fmaf(w1, f1.x, ax); ay = fmaf(w1, f1.y, ay);
        ax = fmaf(w2, f2.x, ax); ay = fmaf(w2, f2.y, ay);
        ax = fmaf(w3, f3.x, ax); ay = fmaf(w3, f3.y, ay);
        ax = fmaf(w4, f4.x, ax); ay = fmaf(w4, f4.y, ay);
        ax = fmaf(w5, f5.x, ax); ay = fmaf(w5, f5.y, ay);
        ax = fmaf(w6, f6.x, ax); ay = fmaf(w6, f6.y, ay);
        ax = fmaf(w7, f7.x, ax); ay = fmaf(w7, f7.y, ay);
    }
    // 4-edge group
    for (; e + 3 < end; e += 4) {
        uint4 c0 = __ldg(reinterpret_cast<const uint4*>(gCsrP + e));
        float2 f0 = __half22float2(__ldg(x + (size_t)(c0.x & 0xffffu) * 32 + lane));
        float2 f1 = __half22float2(__ldg(x + (size_t)(c0.y & 0xffffu) * 32 + lane));
        float2 f2 = __half22float2(__ldg(x + (size_t)(c0.z & 0xffffu) * 32 + lane));
        float2 f3 = __half22float2(__ldg(x + (size_t)(c0.w & 0xffffu) * 32 + lane));
        float w0 = __half2float(__ushort_as_half((unsigned short)(c0.x >> 16)));
        float w1 = __half2float(__ushort_as_half((unsigned short)(c0.y >> 16)));
        float w2 = __half2float(__ushort_as_half((unsigned short)(c0.z >> 16)));
        float w3 = __half2float(__ushort_as_half((unsigned short)(c0.w >> 16)));
        ax = fmaf(w0, f0.x, ax); ay = fmaf(w0, f0.y, ay);
        ax = fmaf(w1, f1.x, ax); ay = fmaf(w1, f1.y, ay);
        ax = fmaf(w2, f2.x, ax); ay = fmaf(w2, f2.y, ay);
        ax = fmaf(w3, f3.x, ax); ay = fmaf(w3, f3.y, ay);
    }
    // tail
    for (; e < end; e++) {
        unsigned int v = __ldg(&gCsrP[e]);
        float w = __half2float(__ushort_as_half((unsigned short)(v >> 16)));
        float2 f = __half22float2(__ldg(x + (size_t)(v & 0xffffu) * 32 + lane));
        ax = fmaf(w, f.x, ax); ay = fmaf(w, f.y, ay);
    }

    float rx = wscale * ax, ry = wscale * ay;
    if (addv) {
        float2 a = __half22float2(__ldg(addv + (size_t)warp * 32 + lane));
        rx = fmaf(ascale, a.x, rx);
        ry = fmaf(ascale, a.y, ry);
    }
    if (bias) {
        float2 b = reinterpret_cast<const float2*>(bias)[lane];
        rx = fmaf(bscale, b.x, rx);
        ry = fmaf(bscale, b.y, ry);
    }
    if (HALF_OUT) {
        reinterpret_cast<__half2*>(outv)[(size_t)warp * 32 + lane] = __floats2half2_rn(rx, ry);
    } else {
        reinterpret_cast<float2*>(outv)[(size_t)warp * 32 + lane] = make_float2(rx, ry);
    }
}

__global__ void fill_tail(float* __restrict__ out, int start, int total)
{
    int i = start + blockIdx.x * blockDim.x + threadIdx.x;
    if (i < total) out[i] = 10.0f;
}

extern "C" void kernel_launch(void* const* d_in, const int* in_sizes, int n_in,
                              void* d_out, int out_size)
{
    const float* features = (const float*)d_in[0];
    const void*  ei       = d_in[1];
    const float* ew       = (const float*)d_in[2];
    const float* W1       = (const float*)d_in[3];
    const float* b1       = (const float*)d_in[4];
    const float* W2       = (const float*)d_in[5];
    const float* b2       = (const float*)d_in[6];
    float*       out      = (float*)d_out;

    const int N = in_sizes[0] / IN_DIM;
    const int E = in_sizes[2];

    __half *X0, *P, *H, *A, *B;
    float  *Wc, *C;
    cudaGetSymbolAddress((void**)&X0, gX0);
    cudaGetSymbolAddress((void**)&P,  gP);
    cudaGetSymbolAddress((void**)&H,  gH);
    cudaGetSymbolAddress((void**)&A,  gA);
    cudaGetSymbolAddress((void**)&B,  gB);
    cudaGetSymbolAddress((void**)&Wc, gWc);
    cudaGetSymbolAddress((void**)&C,  gC);
    int* countPtr;
    cudaGetSymbolAddress((void**)&countPtr, gCount);

    // lazily-created side stream + events (host objects only)
    static cudaStream_t sCsr = nullptr;
    static cudaEvent_t  evFork = nullptr, evCsr = nullptr;
    if (!sCsr) {
        cudaStreamCreateWithFlags(&sCsr, cudaStreamNonBlocking);
        cudaEventCreateWithFlags(&evFork, cudaEventDisableTiming);
        cudaEventCreateWithFlags(&evCsr,  cudaEventDisableTiming);
    }

    // ---- fork: CSR build on side stream ----
    cudaEventRecord(evFork, 0);
    cudaStreamWaitEvent(sCsr, evFork, 0);
    detect_idx_dtype<<<1, 1, 0, sCsr>>>(ei, N);
    cudaMemsetAsync(countPtr, 0, (size_t)N * sizeof(int), sCsr);
    hist_dst<<<((E + 1) / 2 + 255) / 256, 256, 0, sCsr>>>(ei, E);
    scan_rowptr<<<1, 1024, 0, sCsr>>>(N, E);
    fill_csr<<<((E + 1) / 2 + 255) / 256, 256, 0, sCsr>>>(ei, ew, E);
    cudaEventRecord(evCsr, sCsr);

    // ---- main stream: combined weights + tensor-core GEMM ----
    {
        int tot = IN_DIM * OUT_DIM + OUT_DIM;
        combine_weights<<<(tot + 255) / 256, 256>>>(W1, b1, W2);
    }
    gemm_mma<<<(N + 63) / 64, 128>>>(N, features, Wc, X0);

    // ---- join ----
    cudaStreamWaitEvent(0, evCsr, 0);

    const int gthreads = 256;
    const int wpb = gthreads / 32;
    const int gblocks = (N + wpb - 1) / wpb;
    const float inv = 1.0f / PSCALE;   // 0.25

    // Ps = (prop(X0) + c)/4            [stored scale 4]
    gather64h<true><<<gblocks, gthreads>>>((const __half2*)X0, P, nullptr, C,
                                           N, inv, 0.0f, inv);
    // Hs = (prop(4*Ps) + b2)/16        [stored scale 16]
    gather64h<true><<<gblocks, gthreads>>>((const __half2*)P, H, nullptr, b2,
                                           N, inv, 0.0f, inv * inv);

    // ---- APPNP: y_{k+1} = (0.9/4)*prop(y_k) + (0.1/4^{k+1})*Hs ----
    const __half* xcur = H;
    float hscale = ALPHA_F;
    for (int k = 0; k < K_STEPS; k++) {
        if (k == K_STEPS - 1) {
            const float wfin = (1.0f - ALPHA_F) * 16.0f * 262144.0f;  // 0.9*16*4^9
            const float afin = ALPHA_F * 16.0f;                        // 1.6
            gather64h<false><<<gblocks, gthreads>>>((const __half2*)xcur, out,
                                                    (const __half2*)H, nullptr,
                                                    N, wfin, afin, 0.0f);
        } else {
            hscale *= inv;
            __half* xnext = (k & 1) ? B : A;
            gather64h<true><<<gblocks, gthreads>>>((const __half2*)xcur, xnext,
                                                   (const __half2*)H, nullptr,
                                                   N, (1.0f - ALPHA_F) * inv, hscale, 0.0f);
            xcur = xnext;
        }
    }

    // tail (reference returns (x, 10); fill any extra outputs with 10)
    int tail = out_size - N * OUT_DIM;
    if (tail > 0)
        fill_tail<<<(tail + 255) / 256, 256>>>(out, N * OUT_DIM, out_size);
}